// round 1
// baseline (speedup 1.0000x reference)
#include <cuda_runtime.h>
#include <math.h>

// ---------------------------------------------------------------------------
// Problem constants
// ---------------------------------------------------------------------------
// B=4, H=W=64, DIM=768, HEADS=12, HEAD=64, WIN=14
// padded Hp=Wp=70 -> 5x5 windows/image -> 100 windows, N=196 tokens/window
// TOKS = 100*196 = 19600 window-token rows, PIX = 4*64*64 = 16384 pixel rows
#define TOKS 19600
#define PIX  16384
#define NBH  1200     // 100 windows * 12 heads
#define NTOK 196
#define KPAD 224      // 196 padded up to 7*32 for the attention k-slots

// ---------------------------------------------------------------------------
// Scratch (static __device__ arrays; no allocation anywhere)
// ---------------------------------------------------------------------------
__device__ float g_win   [19600u * 768u];        // LN1 + window partition
__device__ float g_qkv   [3u * 1200u * 196u * 64u]; // [which][bh][n][d]
__device__ float g_relh  [1200u * 196u * 14u];
__device__ float g_relw  [1200u * 196u * 14u];
__device__ float g_attnout[19600u * 768u];       // [win][n][head*64+d]
__device__ float g_x1    [16384u * 768u];        // x + attn (residual 1)
__device__ float g_ln2   [16384u * 768u];
__device__ float g_mlp   [16384u * 3072u];       // gelu(ln2 @ w1 + b1)

// ---------------------------------------------------------------------------
// f32x2 packed-FMA helpers (Blackwell: doubles fp32 FMA throughput vs FFMA)
// ---------------------------------------------------------------------------
__device__ __forceinline__ unsigned long long dup2(float a) {
    unsigned long long r;
    asm("mov.b64 %0, {%1, %1};" : "=l"(r) : "f"(a));
    return r;
}
__device__ __forceinline__ void fma2(unsigned long long& d,
                                     unsigned long long a,
                                     unsigned long long b) {
    asm("fma.rn.f32x2 %0, %1, %2, %0;" : "+l"(d) : "l"(a), "l"(b));
}
__device__ __forceinline__ float2 unpack2(unsigned long long v) {
    float2 r;
    asm("mov.b64 {%0, %1}, %2;" : "=f"(r.x), "=f"(r.y) : "l"(v));
    return r;
}
__device__ __forceinline__ float gelu_exact(float x) {
    return 0.5f * x * (1.0f + erff(x * 0.70710678118654752440f));
}

// ---------------------------------------------------------------------------
// LayerNorm (+ optional window-partition gather).  One block per output row.
// partition=1: out rows are the 19600 window-token rows (zeros for padding).
// partition=0: out rows are the 16384 pixel rows.
// ---------------------------------------------------------------------------
__global__ void ln_kernel(const float* __restrict__ in,
                          const float* __restrict__ gamma,
                          const float* __restrict__ beta,
                          float* __restrict__ out, int partition) {
    __shared__ float red_s[8], red_q[8];
    int r = blockIdx.x;
    int t = threadIdx.x;
    const float* src;
    float* dst = out + (size_t)r * 768;

    if (partition) {
        int wid = r / 196, n = r % 196;
        int b = wid / 25, wi = (wid % 25) / 5, wj = wid % 5;
        int hh = wi * 14 + n / 14, ww = wj * 14 + n % 14;
        if (hh >= 64 || ww >= 64) {         // padded token -> zeros
            for (int c = t; c < 768; c += 256) dst[c] = 0.0f;
            return;
        }
        src = in + ((size_t)((b * 64 + hh) * 64 + ww)) * 768;
    } else {
        src = in + (size_t)r * 768;
    }

    float v0 = src[t], v1 = src[t + 256], v2 = src[t + 512];
    float s = v0 + v1 + v2;
    float q = v0 * v0 + v1 * v1 + v2 * v2;
    #pragma unroll
    for (int off = 16; off > 0; off >>= 1) {
        s += __shfl_xor_sync(0xffffffffu, s, off);
        q += __shfl_xor_sync(0xffffffffu, q, off);
    }
    int warp = t >> 5, lane = t & 31;
    if (lane == 0) { red_s[warp] = s; red_q[warp] = q; }
    __syncthreads();
    float st = 0.f, qt = 0.f;
    #pragma unroll
    for (int i = 0; i < 8; i++) { st += red_s[i]; qt += red_q[i]; }
    float mean = st * (1.0f / 768.0f);
    float var  = qt * (1.0f / 768.0f) - mean * mean;
    float rstd = rsqrtf(var + 1e-5f);
    dst[t]       = (v0 - mean) * rstd * gamma[t]       + beta[t];
    dst[t + 256] = (v1 - mean) * rstd * gamma[t + 256] + beta[t + 256];
    dst[t + 512] = (v2 - mean) * rstd * gamma[t + 512] + beta[t + 512];
}

// ---------------------------------------------------------------------------
// Decomposed rel-pos bias precompute.
// mode 0: relh[bh, qi*14+qj, ki] = sum_c q[bh,row,c] * rel_pos_h[qi-ki+13, c]
// mode 1: relw[bh, qi*14+qj, kj] = sum_c q[bh,row,c] * rel_pos_w[qj-kj+13, c]
// grid (14, 1200, 2), block 196:  a = blockIdx.x (qi for h-mode, qj for w-mode)
// ---------------------------------------------------------------------------
__global__ void relpos_kernel(const float* __restrict__ qkv,
                              const float* __restrict__ rph,
                              const float* __restrict__ rpw,
                              float* __restrict__ relh,
                              float* __restrict__ relw) {
    int a = blockIdx.x;         // 0..13
    int bh = blockIdx.y;
    int mode = blockIdx.z;
    int t = threadIdx.x;        // 0..195
    int u = t / 14, kk = t % 14;
    const float* qp = qkv + (size_t)bh * NTOK * 64;   // q block (which=0)
    if (mode == 0) {
        int row = a * 14 + u;   // qi=a, qj=u, ki=kk
        const float* rp = rph + (a - kk + 13) * 64;
        const float* qr = qp + (size_t)row * 64;
        float s = 0.f;
        #pragma unroll 8
        for (int c = 0; c < 64; c++) s += qr[c] * rp[c];
        relh[((size_t)bh * NTOK + row) * 14 + kk] = s;
    } else {
        int row = u * 14 + a;   // qi=u, qj=a, kj=kk
        const float* rp = rpw + (a - kk + 13) * 64;
        const float* qr = qp + (size_t)row * 64;
        float s = 0.f;
        #pragma unroll 8
        for (int c = 0; c < 64; c++) s += qr[c] * rp[c];
        relw[((size_t)bh * NTOK + row) * 14 + kk] = s;
    }
}

// ---------------------------------------------------------------------------
// Fused attention: one block per (window,head).  256 threads, ~184KB smem.
// S = 0.125*Q@K^T + relh + relw ; softmax ; O = P@V ; scatter to [win,n,DIM].
// ---------------------------------------------------------------------------
#define KS_OFF 0
#define VS_OFF (KPAD * 65)                       // 14560
#define QS_OFF (VS_OFF + NTOK * 65)              // 27300
#define PS_OFF (QS_OFF + NTOK * 64)              // 39844
#define ATTN_SMEM_FLOATS (PS_OFF + 8 * 4 * KPAD) // 47012
#define ATTN_SMEM_BYTES (ATTN_SMEM_FLOATS * 4)   // 188048

__global__ void attn_kernel(const float* __restrict__ qkv,
                            const float* __restrict__ relh,
                            const float* __restrict__ relw,
                            float* __restrict__ out) {
    extern __shared__ float sm[];
    float* Ks = sm + KS_OFF;   // [224][65]  (rows 196..223 zero)
    float* Vs = sm + VS_OFF;   // [196][65]
    float* Qs = sm + QS_OFF;   // [196][64]
    float* Ps = sm + PS_OFF;   // [8 warps][4 rows][224]

    int bh = blockIdx.x;
    int tid = threadIdx.x, warp = tid >> 5, lane = tid & 31;
    const float* qp = qkv + ((size_t)0 * NBH + bh) * NTOK * 64;
    const float* kp = qkv + ((size_t)1 * NBH + bh) * NTOK * 64;
    const float* vp = qkv + ((size_t)2 * NBH + bh) * NTOK * 64;

    for (int idx = tid; idx < NTOK * 64; idx += 256) {
        int row = idx >> 6, c = idx & 63;
        Ks[row * 65 + c] = kp[idx];
        Vs[row * 65 + c] = vp[idx];
        Qs[idx]          = qp[idx];
    }
    for (int idx = tid; idx < (KPAD - NTOK) * 64; idx += 256)
        Ks[(NTOK + (idx >> 6)) * 65 + (idx & 63)] = 0.0f;
    __syncthreads();

    int win = bh / 12, h = bh % 12;
    float* outbase = out + (size_t)win * NTOK * 768 + h * 64;

    // per-lane k-slot metadata (same for every chunk)
    int kk[7], ki[7], kj[7]; bool kvalid[7];
    #pragma unroll
    for (int s = 0; s < 7; s++) {
        kk[s] = lane + 32 * s;
        kvalid[s] = (kk[s] < NTOK);
        int kc = kvalid[s] ? kk[s] : 0;
        ki[s] = kc / 14; kj[s] = kc % 14;
    }

    // 49 chunks of 4 q-rows, distributed round-robin over 8 warps
    for (int chunk = warp; chunk < 49; chunk += 8) {
        int row0 = chunk * 4;
        float acc[4][7];
        #pragma unroll
        for (int r = 0; r < 4; r++)
            #pragma unroll
            for (int s = 0; s < 7; s++) acc[r][s] = 0.f;

        #pragma unroll 4
        for (int c = 0; c < 64; c++) {
            float q0 = Qs[(row0 + 0) * 64 + c];
            float q1 = Qs[(row0 + 1) * 64 + c];
            float q2 = Qs[(row0 + 2) * 64 + c];
            float q3 = Qs[(row0 + 3) * 64 + c];
            #pragma unroll
            for (int s = 0; s < 7; s++) {
                float kv = Ks[(lane + 32 * s) * 65 + c];
                acc[0][s] = fmaf(q0, kv, acc[0][s]);
                acc[1][s] = fmaf(q1, kv, acc[1][s]);
                acc[2][s] = fmaf(q2, kv, acc[2][s]);
                acc[3][s] = fmaf(q3, kv, acc[3][s]);
            }
        }

        // bias + softmax, write P to this warp's smem strip
        #pragma unroll
        for (int r = 0; r < 4; r++) {
            int row = row0 + r;
            const float* rh = relh + ((size_t)bh * NTOK + row) * 14;
            const float* rw = relw + ((size_t)bh * NTOK + row) * 14;
            float v[7]; float m = -1e30f;
            #pragma unroll
            for (int s = 0; s < 7; s++) {
                v[s] = kvalid[s] ? (acc[r][s] * 0.125f + rh[ki[s]] + rw[kj[s]])
                                 : -1e30f;
                m = fmaxf(m, v[s]);
            }
            #pragma unroll
            for (int off = 16; off > 0; off >>= 1)
                m = fmaxf(m, __shfl_xor_sync(0xffffffffu, m, off));
            float sum = 0.f;
            #pragma unroll
            for (int s = 0; s < 7; s++) {
                float e = __expf(v[s] - m);
                v[s] = e; sum += e;
            }
            #pragma unroll
            for (int off = 16; off > 0; off >>= 1)
                sum += __shfl_xor_sync(0xffffffffu, sum, off);
            float inv = 1.0f / sum;
            #pragma unroll
            for (int s = 0; s < 7; s++)
                Ps[(warp * 4 + r) * KPAD + kk[s]] = v[s] * inv;
        }
        __syncwarp();

        // O = P @ V : each lane does d = lane and lane+32 for 4 rows
        float o[4][2];
        #pragma unroll
        for (int r = 0; r < 4; r++) { o[r][0] = 0.f; o[r][1] = 0.f; }
        #pragma unroll 2
        for (int k2 = 0; k2 < NTOK; k2++) {
            float va = Vs[k2 * 65 + lane];
            float vb = Vs[k2 * 65 + lane + 32];
            #pragma unroll
            for (int r = 0; r < 4; r++) {
                float p = Ps[(warp * 4 + r) * KPAD + k2];
                o[r][0] = fmaf(p, va, o[r][0]);
                o[r][1] = fmaf(p, vb, o[r][1]);
            }
        }
        #pragma unroll
        for (int r = 0; r < 4; r++) {
            float* op = outbase + (size_t)(row0 + r) * 768;
            op[lane]      = o[r][0];
            op[lane + 32] = o[r][1];
        }
        __syncwarp();
    }
}

// ---------------------------------------------------------------------------
// Generic fp32 GEMM, 128x128x16 tile, 256 threads, 8x8/thread via f32x2 FMA.
// C = A[M,K] @ B[K,N] (+bias, + epilogue).  N%128==0, K%16==0 required.
// Epilogues:
//   0: scatter into g_qkv layout  (C = g_qkv)
//   1: proj: un-partition + residual add:  C[pix] = extra[pix] + val  (skip pad)
//   2: GELU:                              C[r*N+c] = gelu(val)
//   3: residual:                          C[r*N+c] = val + extra[r*N+c]
// ---------------------------------------------------------------------------
#define BM 128
#define BN 128
#define BK 16

template <int EPI>
__global__ __launch_bounds__(256, 2)
void gemm_kernel(const float* __restrict__ A, const float* __restrict__ B,
                 const float* __restrict__ bias, float* __restrict__ C,
                 const float* __restrict__ extra, int M, int N, int K) {
    __shared__ float As[BK][BM];
    __shared__ float Bs[BK][BN];

    int tid = threadIdx.x;
    int bm = blockIdx.y * BM;
    int bn = blockIdx.x * BN;

    // A-tile loader: rows (tid>>2) and (tid>>2)+64 ; k-chunk (tid&3)*4
    int arow = tid >> 2;
    int ak   = (tid & 3) * 4;
    // B-tile loader: k rows (tid>>5) and (tid>>5)+8 ; cols (tid&31)*4
    int bkr = tid >> 5;
    int bc  = (tid & 31) * 4;

    // compute mapping: warps 4x2, lanes 4x8, 8x8 per thread
    int warp = tid >> 5, lane = tid & 31;
    int tr = (warp >> 1) * 32 + (lane >> 3) * 8;
    int tc = (warp & 1) * 64 + (lane & 7) * 8;

    unsigned long long acc[8][4];
    #pragma unroll
    for (int i = 0; i < 8; i++)
        #pragma unroll
        for (int j = 0; j < 4; j++) acc[i][j] = 0ull;

    float4 ar0, ar1, br0, br1;
    const float4 z4 = make_float4(0.f, 0.f, 0.f, 0.f);

    int r0 = bm + arow, r1 = bm + arow + 64;
    const float* Ap0 = A + (size_t)r0 * K + ak;
    const float* Ap1 = A + (size_t)r1 * K + ak;
    const float* Bp0 = B + (size_t)bkr * N + bn + bc;
    const float* Bp1 = B + (size_t)(bkr + 8) * N + bn + bc;

    // prefetch tile 0
    ar0 = (r0 < M) ? *(const float4*)(Ap0) : z4;
    ar1 = (r1 < M) ? *(const float4*)(Ap1) : z4;
    br0 = *(const float4*)(Bp0);
    br1 = *(const float4*)(Bp1);

    int nt = K / BK;
    for (int t = 0; t < nt; t++) {
        // store staged tile
        As[ak + 0][arow] = ar0.x; As[ak + 1][arow] = ar0.y;
        As[ak + 2][arow] = ar0.z; As[ak + 3][arow] = ar0.w;
        As[ak + 0][arow + 64] = ar1.x; As[ak + 1][arow + 64] = ar1.y;
        As[ak + 2][arow + 64] = ar1.z; As[ak + 3][arow + 64] = ar1.w;
        *(float4*)&Bs[bkr][bc]     = br0;
        *(float4*)&Bs[bkr + 8][bc] = br1;
        __syncthreads();

        // prefetch next tile while computing
        if (t + 1 < nt) {
            int koff = (t + 1) * BK;
            ar0 = (r0 < M) ? *(const float4*)(Ap0 + koff) : z4;
            ar1 = (r1 < M) ? *(const float4*)(Ap1 + koff) : z4;
            br0 = *(const float4*)(Bp0 + (size_t)koff * N);
            br1 = *(const float4*)(Bp1 + (size_t)koff * N);
        }

        #pragma unroll
        for (int kkx = 0; kkx < BK; kkx++) {
            float4 a0 = *(const float4*)&As[kkx][tr];
            float4 a1 = *(const float4*)&As[kkx][tr + 4];
            float4 b0 = *(const float4*)&Bs[kkx][tc];
            float4 b1 = *(const float4*)&Bs[kkx][tc + 4];
            unsigned long long bp[4];
            bp[0] = ((const unsigned long long*)&b0)[0];
            bp[1] = ((const unsigned long long*)&b0)[1];
            bp[2] = ((const unsigned long long*)&b1)[0];
            bp[3] = ((const unsigned long long*)&b1)[1];
            float av[8] = {a0.x, a0.y, a0.z, a0.w, a1.x, a1.y, a1.z, a1.w};
            #pragma unroll
            for (int i = 0; i < 8; i++) {
                unsigned long long ad = dup2(av[i]);
                #pragma unroll
                for (int j = 0; j < 4; j++) fma2(acc[i][j], ad, bp[j]);
            }
        }
        __syncthreads();
    }

    // ---------------- epilogue ----------------
    #pragma unroll
    for (int i = 0; i < 8; i++) {
        int r = bm + tr + i;
        if (r >= M) continue;
        int win = 0, n = 0;
        if (EPI == 0 || EPI == 1) { win = r / 196; n = r % 196; }
        #pragma unroll
        for (int j = 0; j < 4; j++) {
            float2 f = unpack2(acc[i][j]);
            int g = bn + tc + 2 * j;
            float vx = f.x + bias[g];
            float vy = f.y + bias[g + 1];
            if (EPI == 0) {
                int which = g / 768;
                int rem = g - which * 768;
                int hh = rem >> 6, d = rem & 63;
                size_t base = ((((size_t)which * NBH) + (size_t)win * 12 + hh)
                               * NTOK + n) * 64 + d;
                *(float2*)&C[base] = make_float2(vx, vy);
            } else if (EPI == 1) {
                int b = win / 25, wi = (win % 25) / 5, wj = win % 5;
                int ph = wi * 14 + n / 14, pw = wj * 14 + n % 14;
                if (ph < 64 && pw < 64) {
                    size_t idx = ((size_t)((b * 64 + ph) * 64 + pw)) * 768 + g;
                    *(float2*)&C[idx] =
                        make_float2(extra[idx] + vx, extra[idx + 1] + vy);
                }
            } else if (EPI == 2) {
                size_t idx = (size_t)r * N + g;
                *(float2*)&C[idx] = make_float2(gelu_exact(vx), gelu_exact(vy));
            } else {  // EPI == 3
                size_t idx = (size_t)r * N + g;
                *(float2*)&C[idx] =
                    make_float2(vx + extra[idx], vy + extra[idx + 1]);
            }
        }
    }
}

// ---------------------------------------------------------------------------
// Launch
// ---------------------------------------------------------------------------
static float* sym_addr(const void* sym) {
    void* p = nullptr;
    cudaGetSymbolAddress(&p, sym);
    return (float*)p;
}

extern "C" void kernel_launch(void* const* d_in, const int* in_sizes, int n_in,
                              void* d_out, int out_size) {
    const float* x     = (const float*)d_in[0];
    const float* n1g   = (const float*)d_in[1];
    const float* n1b   = (const float*)d_in[2];
    const float* qkvw  = (const float*)d_in[3];
    const float* qkvb  = (const float*)d_in[4];
    const float* projw = (const float*)d_in[5];
    const float* projb = (const float*)d_in[6];
    const float* rph   = (const float*)d_in[7];
    const float* rpw   = (const float*)d_in[8];
    const float* n2g   = (const float*)d_in[9];
    const float* n2b   = (const float*)d_in[10];
    const float* w1    = (const float*)d_in[11];
    const float* b1    = (const float*)d_in[12];
    const float* w2    = (const float*)d_in[13];
    const float* b2    = (const float*)d_in[14];
    float* out = (float*)d_out;

    float* p_win  = sym_addr(g_win);
    float* p_qkv  = sym_addr(g_qkv);
    float* p_relh = sym_addr(g_relh);
    float* p_relw = sym_addr(g_relw);
    float* p_att  = sym_addr(g_attnout);
    float* p_x1   = sym_addr(g_x1);
    float* p_ln2  = sym_addr(g_ln2);
    float* p_mlp  = sym_addr(g_mlp);

    cudaFuncSetAttribute(attn_kernel,
                         cudaFuncAttributeMaxDynamicSharedMemorySize,
                         ATTN_SMEM_BYTES);

    // 1) LN1 + window partition (padded rows -> zeros)
    ln_kernel<<<TOKS, 256>>>(x, n1g, n1b, p_win, 1);

    // 2) QKV GEMM: [19600,768] @ [768,2304], scatter to q/k/v layout
    gemm_kernel<0><<<dim3(2304 / BN, (TOKS + BM - 1) / BM), 256>>>(
        p_win, qkvw, qkvb, p_qkv, nullptr, TOKS, 2304, 768);

    // 3) decomposed rel-pos bias precompute
    relpos_kernel<<<dim3(14, NBH, 2), 196>>>(p_qkv, rph, rpw, p_relh, p_relw);

    // 4) fused attention (S + bias + softmax + P@V)
    attn_kernel<<<NBH, 256, ATTN_SMEM_BYTES>>>(p_qkv, p_relh, p_relw, p_att);

    // 5) proj GEMM + un-partition + residual add -> x1
    gemm_kernel<1><<<dim3(768 / BN, (TOKS + BM - 1) / BM), 256>>>(
        p_att, projw, projb, p_x1, x, TOKS, 768, 768);

    // 6) LN2
    ln_kernel<<<PIX, 256>>>(p_x1, n2g, n2b, p_ln2, 0);

    // 7) MLP fc1 + exact GELU
    gemm_kernel<2><<<dim3(3072 / BN, PIX / BM), 256>>>(
        p_ln2, w1, b1, p_mlp, nullptr, PIX, 3072, 768);

    // 8) MLP fc2 + residual -> final output
    gemm_kernel<3><<<dim3(768 / BN, PIX / BM), 256>>>(
        p_mlp, w2, b2, out, p_x1, PIX, 768, 3072);

    (void)in_sizes; (void)n_in; (void)out_size;
}

// round 3
// speedup vs baseline: 1.9498x; 1.9498x over previous
#include <cuda_runtime.h>
#include <cuda_bf16.h>
#include <math.h>
#include <stdint.h>

// ---------------------------------------------------------------------------
// Problem constants
// ---------------------------------------------------------------------------
#define TOKS 19600
#define PIX  16384
#define NBH  1200
#define NTOK 196
#define KPAD 224

// ---------------------------------------------------------------------------
// Scratch (static __device__ arrays; no allocation anywhere)
// ---------------------------------------------------------------------------
__device__ float g_qkv [3u * 1200u * 196u * 64u];   // [which][bh][n][d] fp32
__device__ float g_relh[1200u * 196u * 14u];
__device__ float g_relw[1200u * 196u * 14u];
__device__ float g_x1  [16384u * 768u];             // residual-1 (fp32)

__device__ __align__(256) __nv_bfloat16 g_win_hi[19600u * 768u];
__device__ __align__(256) __nv_bfloat16 g_win_lo[19600u * 768u];
__device__ __align__(256) __nv_bfloat16 g_att_hi[19600u * 768u];
__device__ __align__(256) __nv_bfloat16 g_att_lo[19600u * 768u];
__device__ __align__(256) __nv_bfloat16 g_ln2_hi[16384u * 768u];
__device__ __align__(256) __nv_bfloat16 g_ln2_lo[16384u * 768u];
__device__ __align__(256) __nv_bfloat16 g_mlp_hi[16384u * 3072u];
__device__ __align__(256) __nv_bfloat16 g_mlp_lo[16384u * 3072u];
// transposed (N-major, K contiguous) weight splits
__device__ __align__(256) __nv_bfloat16 g_qkvwt_hi[2304u * 768u];
__device__ __align__(256) __nv_bfloat16 g_qkvwt_lo[2304u * 768u];
__device__ __align__(256) __nv_bfloat16 g_projwt_hi[768u * 768u];
__device__ __align__(256) __nv_bfloat16 g_projwt_lo[768u * 768u];
__device__ __align__(256) __nv_bfloat16 g_w1t_hi[3072u * 768u];
__device__ __align__(256) __nv_bfloat16 g_w1t_lo[3072u * 768u];
__device__ __align__(256) __nv_bfloat16 g_w2t_hi[768u * 3072u];
__device__ __align__(256) __nv_bfloat16 g_w2t_lo[768u * 3072u];

// ---------------------------------------------------------------------------
// PTX helpers — sm_80-era features only (NO sm_103a-gated instructions:
// the harness PTX pass targets plain sm_103, which rejects tcgen05/TMEM).
// ---------------------------------------------------------------------------
__device__ __forceinline__ uint32_t smem_u32(const void* p) {
    uint32_t a;
    asm("{ .reg .u64 t; cvta.to.shared.u64 t, %1; cvt.u32.u64 %0, t; }"
        : "=r"(a) : "l"(p));
    return a;
}
__device__ __forceinline__ void cp_async16(uint32_t s, const void* g, uint32_t sz) {
    asm volatile("cp.async.cg.shared.global [%0], [%1], 16, %2;"
                 :: "r"(s), "l"(g), "r"(sz) : "memory");
}
__device__ __forceinline__ void cp_commit() {
    asm volatile("cp.async.commit_group;" ::: "memory");
}
template <int N> __device__ __forceinline__ void cp_wait() {
    asm volatile("cp.async.wait_group %0;" :: "n"(N) : "memory");
}
__device__ __forceinline__ void ldsm4(uint32_t* r, uint32_t addr) {
    asm volatile("ldmatrix.sync.aligned.m8n8.x4.shared.b16 {%0,%1,%2,%3}, [%4];"
                 : "=r"(r[0]), "=r"(r[1]), "=r"(r[2]), "=r"(r[3]) : "r"(addr));
}
__device__ __forceinline__ void mma16816(float* c, const uint32_t* a,
                                         const uint32_t* b) {
    asm volatile(
        "mma.sync.aligned.m16n8k16.row.col.f32.bf16.bf16.f32 "
        "{%0,%1,%2,%3}, {%4,%5,%6,%7}, {%8,%9}, {%0,%1,%2,%3};"
        : "+f"(c[0]), "+f"(c[1]), "+f"(c[2]), "+f"(c[3])
        : "r"(a[0]), "r"(a[1]), "r"(a[2]), "r"(a[3]), "r"(b[0]), "r"(b[1]));
}
__device__ __forceinline__ float gelu_exact(float x) {
    return 0.5f * x * (1.0f + erff(x * 0.70710678118654752440f));
}
__device__ __forceinline__ void split_bf16(float v, __nv_bfloat16& h, __nv_bfloat16& l) {
    h = __float2bfloat16(v);
    l = __float2bfloat16(v - __bfloat162float(h));
}

// ---------------------------------------------------------------------------
// LayerNorm (+ optional window-partition gather), emits bf16 hi/lo pair.
// ---------------------------------------------------------------------------
__global__ void ln_kernel(const float* __restrict__ in,
                          const float* __restrict__ gamma,
                          const float* __restrict__ beta,
                          __nv_bfloat16* __restrict__ ohi,
                          __nv_bfloat16* __restrict__ olo, int partition) {
    __shared__ float red_s[8], red_q[8];
    int r = blockIdx.x, t = threadIdx.x;
    size_t dst = (size_t)r * 768;
    const float* src;
    if (partition) {
        int wid = r / 196, n = r % 196;
        int b = wid / 25, wi = (wid % 25) / 5, wj = wid % 5;
        int hh = wi * 14 + n / 14, ww = wj * 14 + n % 14;
        if (hh >= 64 || ww >= 64) {
            __nv_bfloat16 z = __float2bfloat16(0.0f);
            for (int c = t; c < 768; c += 256) { ohi[dst + c] = z; olo[dst + c] = z; }
            return;
        }
        src = in + ((size_t)((b * 64 + hh) * 64 + ww)) * 768;
    } else {
        src = in + (size_t)r * 768;
    }
    float v0 = src[t], v1 = src[t + 256], v2 = src[t + 512];
    float s = v0 + v1 + v2, q = v0 * v0 + v1 * v1 + v2 * v2;
    #pragma unroll
    for (int off = 16; off > 0; off >>= 1) {
        s += __shfl_xor_sync(0xffffffffu, s, off);
        q += __shfl_xor_sync(0xffffffffu, q, off);
    }
    int warp = t >> 5, lane = t & 31;
    if (lane == 0) { red_s[warp] = s; red_q[warp] = q; }
    __syncthreads();
    float st = 0.f, qt = 0.f;
    #pragma unroll
    for (int i = 0; i < 8; i++) { st += red_s[i]; qt += red_q[i]; }
    float mean = st * (1.0f / 768.0f);
    float var  = qt * (1.0f / 768.0f) - mean * mean;
    float rstd = rsqrtf(var + 1e-5f);
    #pragma unroll
    for (int k = 0; k < 3; k++) {
        int c = t + k * 256;
        float vv = (k == 0 ? v0 : (k == 1 ? v1 : v2));
        float y = (vv - mean) * rstd * gamma[c] + beta[c];
        __nv_bfloat16 h, l; split_bf16(y, h, l);
        ohi[dst + c] = h; olo[dst + c] = l;
    }
}

// ---------------------------------------------------------------------------
// Weight transpose + split: W[K,N] fp32 -> T_hi/T_lo[N,K] bf16
// ---------------------------------------------------------------------------
__global__ void tsplit_kernel(const float* __restrict__ W,
                              __nv_bfloat16* __restrict__ Thi,
                              __nv_bfloat16* __restrict__ Tlo, int Kd, int Nd) {
    __shared__ float tile[32][33];
    int n0 = blockIdx.x * 32, k0 = blockIdx.y * 32;
    int tx = threadIdx.x & 31, ty = threadIdx.x >> 5;
    #pragma unroll
    for (int i = 0; i < 4; i++)
        tile[ty + i * 8][tx] = W[(size_t)(k0 + ty + i * 8) * Nd + n0 + tx];
    __syncthreads();
    #pragma unroll
    for (int i = 0; i < 4; i++) {
        int n = n0 + ty + i * 8, k = k0 + tx;
        float v = tile[tx][ty + i * 8];
        __nv_bfloat16 h, l; split_bf16(v, h, l);
        Thi[(size_t)n * Kd + k] = h;
        Tlo[(size_t)n * Kd + k] = l;
    }
}

// ---------------------------------------------------------------------------
// Decomposed rel-pos bias precompute (reads fp32 q from g_qkv)
// ---------------------------------------------------------------------------
__global__ void relpos_kernel(const float* __restrict__ qkv,
                              const float* __restrict__ rph,
                              const float* __restrict__ rpw,
                              float* __restrict__ relh,
                              float* __restrict__ relw) {
    int a = blockIdx.x, bh = blockIdx.y, mode = blockIdx.z;
    int t = threadIdx.x;
    int u = t / 14, kk = t % 14;
    const float* qp = qkv + (size_t)bh * NTOK * 64;
    if (mode == 0) {
        int row = a * 14 + u;
        const float* rp = rph + (a - kk + 13) * 64;
        const float* qr = qp + (size_t)row * 64;
        float s = 0.f;
        #pragma unroll 8
        for (int c = 0; c < 64; c++) s += qr[c] * rp[c];
        relh[((size_t)bh * NTOK + row) * 14 + kk] = s;
    } else {
        int row = u * 14 + a;
        const float* rp = rpw + (a - kk + 13) * 64;
        const float* qr = qp + (size_t)row * 64;
        float s = 0.f;
        #pragma unroll 8
        for (int c = 0; c < 64; c++) s += qr[c] * rp[c];
        relw[((size_t)bh * NTOK + row) * 14 + kk] = s;
    }
}

// ---------------------------------------------------------------------------
// Fused attention (fp32 SIMT); emits bf16 hi/lo output.
// ---------------------------------------------------------------------------
#define KS_OFF 0
#define VS_OFF (KPAD * 65)
#define QS_OFF (VS_OFF + NTOK * 65)
#define PS_OFF (QS_OFF + NTOK * 64)
#define ATTN_SMEM_FLOATS (PS_OFF + 8 * 4 * KPAD)
#define ATTN_SMEM_BYTES (ATTN_SMEM_FLOATS * 4)

__global__ void attn_kernel(const float* __restrict__ qkv,
                            const float* __restrict__ relh,
                            const float* __restrict__ relw,
                            __nv_bfloat16* __restrict__ outhi,
                            __nv_bfloat16* __restrict__ outlo) {
    extern __shared__ float sm[];
    float* Ks = sm + KS_OFF;
    float* Vs = sm + VS_OFF;
    float* Qs = sm + QS_OFF;
    float* Ps = sm + PS_OFF;

    int bh = blockIdx.x;
    int tid = threadIdx.x, warp = tid >> 5, lane = tid & 31;
    const float* qp = qkv + ((size_t)0 * NBH + bh) * NTOK * 64;
    const float* kp = qkv + ((size_t)1 * NBH + bh) * NTOK * 64;
    const float* vp = qkv + ((size_t)2 * NBH + bh) * NTOK * 64;

    for (int idx = tid; idx < NTOK * 64; idx += 256) {
        int row = idx >> 6, c = idx & 63;
        Ks[row * 65 + c] = kp[idx];
        Vs[row * 65 + c] = vp[idx];
        Qs[idx]          = qp[idx];
    }
    for (int idx = tid; idx < (KPAD - NTOK) * 64; idx += 256)
        Ks[(NTOK + (idx >> 6)) * 65 + (idx & 63)] = 0.0f;
    __syncthreads();

    int win = bh / 12, h = bh % 12;
    size_t obase = (size_t)win * NTOK * 768 + h * 64;

    int kk[7], ki[7], kj[7]; bool kvalid[7];
    #pragma unroll
    for (int s = 0; s < 7; s++) {
        kk[s] = lane + 32 * s;
        kvalid[s] = (kk[s] < NTOK);
        int kc = kvalid[s] ? kk[s] : 0;
        ki[s] = kc / 14; kj[s] = kc % 14;
    }

    for (int chunk = warp; chunk < 49; chunk += 8) {
        int row0 = chunk * 4;
        float acc[4][7];
        #pragma unroll
        for (int r = 0; r < 4; r++)
            #pragma unroll
            for (int s = 0; s < 7; s++) acc[r][s] = 0.f;

        #pragma unroll 4
        for (int c = 0; c < 64; c++) {
            float q0 = Qs[(row0 + 0) * 64 + c];
            float q1 = Qs[(row0 + 1) * 64 + c];
            float q2 = Qs[(row0 + 2) * 64 + c];
            float q3 = Qs[(row0 + 3) * 64 + c];
            #pragma unroll
            for (int s = 0; s < 7; s++) {
                float kv = Ks[(lane + 32 * s) * 65 + c];
                acc[0][s] = fmaf(q0, kv, acc[0][s]);
                acc[1][s] = fmaf(q1, kv, acc[1][s]);
                acc[2][s] = fmaf(q2, kv, acc[2][s]);
                acc[3][s] = fmaf(q3, kv, acc[3][s]);
            }
        }
        #pragma unroll
        for (int r = 0; r < 4; r++) {
            int row = row0 + r;
            const float* rh = relh + ((size_t)bh * NTOK + row) * 14;
            const float* rw = relw + ((size_t)bh * NTOK + row) * 14;
            float v[7]; float m = -1e30f;
            #pragma unroll
            for (int s = 0; s < 7; s++) {
                v[s] = kvalid[s] ? (acc[r][s] * 0.125f + rh[ki[s]] + rw[kj[s]]) : -1e30f;
                m = fmaxf(m, v[s]);
            }
            #pragma unroll
            for (int off = 16; off > 0; off >>= 1)
                m = fmaxf(m, __shfl_xor_sync(0xffffffffu, m, off));
            float sum = 0.f;
            #pragma unroll
            for (int s = 0; s < 7; s++) { float e = __expf(v[s] - m); v[s] = e; sum += e; }
            #pragma unroll
            for (int off = 16; off > 0; off >>= 1)
                sum += __shfl_xor_sync(0xffffffffu, sum, off);
            float inv = 1.0f / sum;
            #pragma unroll
            for (int s = 0; s < 7; s++)
                Ps[(warp * 4 + r) * KPAD + kk[s]] = v[s] * inv;
        }
        __syncwarp();
        float o[4][2];
        #pragma unroll
        for (int r = 0; r < 4; r++) { o[r][0] = 0.f; o[r][1] = 0.f; }
        #pragma unroll 2
        for (int k2 = 0; k2 < NTOK; k2++) {
            float va = Vs[k2 * 65 + lane];
            float vb = Vs[k2 * 65 + lane + 32];
            #pragma unroll
            for (int r = 0; r < 4; r++) {
                float p = Ps[(warp * 4 + r) * KPAD + k2];
                o[r][0] = fmaf(p, va, o[r][0]);
                o[r][1] = fmaf(p, vb, o[r][1]);
            }
        }
        #pragma unroll
        for (int r = 0; r < 4; r++) {
            size_t op = obase + (size_t)(row0 + r) * 768;
            __nv_bfloat16 ha, la, hb, lb;
            split_bf16(o[r][0], ha, la);
            split_bf16(o[r][1], hb, lb);
            outhi[op + lane] = ha;      outlo[op + lane] = la;
            outhi[op + lane + 32] = hb; outlo[op + lane + 32] = lb;
        }
        __syncwarp();
    }
}

// ---------------------------------------------------------------------------
// HMMA (mma.sync bf16) split-precision GEMM.  Tile 128x128xBK32, 256 threads.
// C[M,N] = (Ahi+Alo)[M,K] @ (Bhi+Blo)^T[N,K]  (3 terms; lo*lo dropped)
// smem per stage: 4 tiles x [128 rows x 40 bf16]  (80B padded rows,
// conflict-free ldmatrix).  Double-buffered cp.async.
// Epilogues: 0 qkv-scatter(fp32)  1 proj+unpartition+residual(fp32)
//            2 gelu -> bf16 hi/lo 3 +residual -> fp32 out
// ---------------------------------------------------------------------------
#define ROWE 40                       // padded row, bf16 elems
#define TILE_E (128 * ROWE)           // 5120 elems per operand tile
#define STAGE_E (4 * TILE_E)          // 20480 elems per stage
#define GEMM_SMEM (2 * STAGE_E * 2)   // bytes = 81920

template <int EPI>
__global__ __launch_bounds__(256)
void tc_gemm(const __nv_bfloat16* __restrict__ Ahi, const __nv_bfloat16* __restrict__ Alo,
             const __nv_bfloat16* __restrict__ Bhi, const __nv_bfloat16* __restrict__ Blo,
             const float* __restrict__ bias, float* __restrict__ Cf,
             __nv_bfloat16* __restrict__ Chi, __nv_bfloat16* __restrict__ Clo,
             const float* __restrict__ extra, int M, int N, int K) {
    extern __shared__ __align__(16) __nv_bfloat16 smb[];
    uint32_t smemb = smem_u32(smb);

    int tid = threadIdx.x;
    int bm = blockIdx.y * 128, bn = blockIdx.x * 128;
    int lane = tid & 31, warp = tid >> 5;
    int wm = warp & 1, wn = warp >> 1;    // warp tile: rows wm*64, cols wn*32

    // ---- per-thread cp.async descriptors: 8 chunks of 16B per stage ----
    uint32_t so[8]; const char* gp[8]; uint32_t sz[8];
    #pragma unroll
    for (int i = 0; i < 8; i++) {
        int tile = i >> 1;                // 0 Ahi, 1 Alo, 2 Bhi, 3 Blo
        int ch = tid + (i & 1) * 256;     // 0..511
        int row = ch >> 2, c = ch & 3;    // 128 rows x 4 chunks
        so[i] = (uint32_t)(tile * TILE_E + row * ROWE + c * 8);   // elems
        const __nv_bfloat16* base;
        int grow; bool valid = true;
        if (tile < 2) { grow = bm + row; valid = (grow < M); base = (tile == 0 ? Ahi : Alo); }
        else          { grow = bn + row; base = (tile == 2 ? Bhi : Blo); }
        gp[i] = (const char*)(base + (size_t)(valid ? grow : 0) * K) + c * 16;
        sz[i] = valid ? 16u : 0u;
    }

    // ---- per-lane ldmatrix row/k offsets ----
    int a_row = (lane & 7) + ((lane >> 3) & 1) * 8;   // within m16
    int a_k   = (lane >> 4) * 8;                      // 0 or 8
    int b_row = (lane & 7) + (lane >> 4) * 8;         // within n16
    int b_k   = ((lane >> 3) & 1) * 8;

    float acc[4][4][4];
    #pragma unroll
    for (int i = 0; i < 4; i++)
        #pragma unroll
        for (int j = 0; j < 4; j++)
            #pragma unroll
            for (int k = 0; k < 4; k++) acc[i][j][k] = 0.f;

    const int nt = K / 32;

    // prologue: stage 0
    #pragma unroll
    for (int i = 0; i < 8; i++) cp_async16(smemb + so[i] * 2, gp[i], sz[i]);
    cp_commit();

    for (int t = 0; t < nt; t++) {
        int s = t & 1;
        if (t + 1 < nt) {
            uint32_t sb = smemb + (uint32_t)((t + 1) & 1) * (STAGE_E * 2);
            uint32_t kb = (uint32_t)(t + 1) * 64;   // bytes along K
            #pragma unroll
            for (int i = 0; i < 8; i++) cp_async16(sb + so[i] * 2, gp[i] + kb, sz[i]);
            cp_commit();
            cp_wait<1>();
        } else {
            cp_wait<0>();
        }
        __syncthreads();

        uint32_t st = smemb + (uint32_t)s * (STAGE_E * 2);
        #pragma unroll
        for (int ks = 0; ks < 32; ks += 16) {
            // B frags: hi tile 2, lo tile 3 ; n-pairs at wn*32 and wn*32+16
            uint32_t Bh[8], Bl[8];
            {
                uint32_t r0 = (uint32_t)((wn * 32 + b_row) * ROWE + ks + b_k) * 2;
                uint32_t r1 = (uint32_t)((wn * 32 + 16 + b_row) * ROWE + ks + b_k) * 2;
                ldsm4(Bh + 0, st + (uint32_t)(2 * TILE_E) * 2 + r0);
                ldsm4(Bh + 4, st + (uint32_t)(2 * TILE_E) * 2 + r1);
                ldsm4(Bl + 0, st + (uint32_t)(3 * TILE_E) * 2 + r0);
                ldsm4(Bl + 4, st + (uint32_t)(3 * TILE_E) * 2 + r1);
            }
            #pragma unroll
            for (int mi = 0; mi < 4; mi++) {
                uint32_t Ah[4], Al[4];
                uint32_t ra = (uint32_t)((wm * 64 + mi * 16 + a_row) * ROWE + ks + a_k) * 2;
                ldsm4(Ah, st + ra);                              // tile 0 (Ahi)
                ldsm4(Al, st + (uint32_t)(TILE_E) * 2 + ra);     // tile 1 (Alo)
                #pragma unroll
                for (int nj = 0; nj < 4; nj++) {
                    mma16816(acc[mi][nj], Ah, &Bh[nj * 2]);
                    mma16816(acc[mi][nj], Ah, &Bl[nj * 2]);
                    mma16816(acc[mi][nj], Al, &Bh[nj * 2]);
                }
            }
        }
        __syncthreads();
    }

    // ---------------- epilogue ----------------
    #pragma unroll
    for (int mi = 0; mi < 4; mi++) {
        int rb = bm + wm * 64 + mi * 16 + (lane >> 2);
        #pragma unroll
        for (int hf = 0; hf < 2; hf++) {
            int r = rb + hf * 8;
            if (r >= M) continue;
            int win = 0, n = 0;
            if (EPI == 0 || EPI == 1) { win = r / 196; n = r % 196; }
            int ph = 0, pw = 0; bool pvalid = true; size_t pixbase = 0;
            if (EPI == 1) {
                int b = win / 25, wi = (win % 25) / 5, wj = win % 5;
                ph = wi * 14 + n / 14; pw = wj * 14 + n % 14;
                pvalid = (ph < 64 && pw < 64);
                pixbase = ((size_t)((b * 64 + ph) * 64 + pw)) * 768;
            }
            #pragma unroll
            for (int nj = 0; nj < 4; nj++) {
                float v0 = acc[mi][nj][hf * 2 + 0];
                float v1 = acc[mi][nj][hf * 2 + 1];
                int col = bn + wn * 32 + nj * 8 + (lane & 3) * 2;
                v0 += bias[col]; v1 += bias[col + 1];
                if (EPI == 0) {
                    int which = col / 768;
                    int rem = col - which * 768;
                    int hh = rem >> 6, d = rem & 63;
                    size_t base = ((((size_t)which * NBH) + (size_t)win * 12 + hh)
                                   * NTOK + n) * 64 + d;
                    *(float2*)&Cf[base] = make_float2(v0, v1);
                } else if (EPI == 1) {
                    if (pvalid) {
                        size_t idx = pixbase + col;
                        float2 e = *(const float2*)(extra + idx);
                        *(float2*)&Cf[idx] = make_float2(v0 + e.x, v1 + e.y);
                    }
                } else if (EPI == 2) {
                    size_t idx = (size_t)r * N + col;
                    float a = gelu_exact(v0), b2 = gelu_exact(v1);
                    __nv_bfloat16 ha, la, hb, lb;
                    split_bf16(a, ha, la);
                    split_bf16(b2, hb, lb);
                    *(__nv_bfloat162*)(Chi + idx) = __nv_bfloat162(ha, hb);
                    *(__nv_bfloat162*)(Clo + idx) = __nv_bfloat162(la, lb);
                } else {
                    size_t idx = (size_t)r * N + col;
                    float2 e = *(const float2*)(extra + idx);
                    *(float2*)&Cf[idx] = make_float2(v0 + e.x, v1 + e.y);
                }
            }
        }
    }
}

// ---------------------------------------------------------------------------
// Launch
// ---------------------------------------------------------------------------
static float* sym_f(const void* s) { void* p = nullptr; cudaGetSymbolAddress(&p, s); return (float*)p; }
static __nv_bfloat16* sym_b(const void* s) { void* p = nullptr; cudaGetSymbolAddress(&p, s); return (__nv_bfloat16*)p; }

extern "C" void kernel_launch(void* const* d_in, const int* in_sizes, int n_in,
                              void* d_out, int out_size) {
    const float* x     = (const float*)d_in[0];
    const float* n1g   = (const float*)d_in[1];
    const float* n1b   = (const float*)d_in[2];
    const float* qkvw  = (const float*)d_in[3];
    const float* qkvb  = (const float*)d_in[4];
    const float* projw = (const float*)d_in[5];
    const float* projb = (const float*)d_in[6];
    const float* rph   = (const float*)d_in[7];
    const float* rpw   = (const float*)d_in[8];
    const float* n2g   = (const float*)d_in[9];
    const float* n2b   = (const float*)d_in[10];
    const float* w1    = (const float*)d_in[11];
    const float* b1    = (const float*)d_in[12];
    const float* w2    = (const float*)d_in[13];
    const float* b2    = (const float*)d_in[14];
    float* out = (float*)d_out;

    float* p_qkv  = sym_f(g_qkv);
    float* p_relh = sym_f(g_relh);
    float* p_relw = sym_f(g_relw);
    float* p_x1   = sym_f(g_x1);
    __nv_bfloat16 *winh = sym_b(g_win_hi),  *winl = sym_b(g_win_lo);
    __nv_bfloat16 *atth = sym_b(g_att_hi),  *attl = sym_b(g_att_lo);
    __nv_bfloat16 *ln2h = sym_b(g_ln2_hi),  *ln2l = sym_b(g_ln2_lo);
    __nv_bfloat16 *mlph = sym_b(g_mlp_hi),  *mlpl = sym_b(g_mlp_lo);
    __nv_bfloat16 *qwh = sym_b(g_qkvwt_hi), *qwl = sym_b(g_qkvwt_lo);
    __nv_bfloat16 *pwh = sym_b(g_projwt_hi),*pwl = sym_b(g_projwt_lo);
    __nv_bfloat16 *w1h = sym_b(g_w1t_hi),   *w1l = sym_b(g_w1t_lo);
    __nv_bfloat16 *w2h = sym_b(g_w2t_hi),   *w2l = sym_b(g_w2t_lo);

    cudaFuncSetAttribute(attn_kernel, cudaFuncAttributeMaxDynamicSharedMemorySize,
                         ATTN_SMEM_BYTES);
    cudaFuncSetAttribute(tc_gemm<0>, cudaFuncAttributeMaxDynamicSharedMemorySize, GEMM_SMEM);
    cudaFuncSetAttribute(tc_gemm<1>, cudaFuncAttributeMaxDynamicSharedMemorySize, GEMM_SMEM);
    cudaFuncSetAttribute(tc_gemm<2>, cudaFuncAttributeMaxDynamicSharedMemorySize, GEMM_SMEM);
    cudaFuncSetAttribute(tc_gemm<3>, cudaFuncAttributeMaxDynamicSharedMemorySize, GEMM_SMEM);

    // 0) weight transpose+split
    tsplit_kernel<<<dim3(2304 / 32, 768 / 32), 256>>>(qkvw, qwh, qwl, 768, 2304);
    tsplit_kernel<<<dim3(768 / 32, 768 / 32), 256>>>(projw, pwh, pwl, 768, 768);
    tsplit_kernel<<<dim3(3072 / 32, 768 / 32), 256>>>(w1, w1h, w1l, 768, 3072);
    tsplit_kernel<<<dim3(768 / 32, 3072 / 32), 256>>>(w2, w2h, w2l, 3072, 768);

    // 1) LN1 + window partition -> bf16 hi/lo
    ln_kernel<<<TOKS, 256>>>(x, n1g, n1b, winh, winl, 1);

    // 2) QKV GEMM -> fp32 q/k/v scatter
    tc_gemm<0><<<dim3(2304 / 128, (TOKS + 127) / 128), 256, GEMM_SMEM>>>(
        winh, winl, qwh, qwl, qkvb, p_qkv, nullptr, nullptr, nullptr,
        TOKS, 2304, 768);

    // 3) rel-pos bias
    relpos_kernel<<<dim3(14, NBH, 2), 196>>>(p_qkv, rph, rpw, p_relh, p_relw);

    // 4) fused attention -> bf16 hi/lo
    attn_kernel<<<NBH, 256, ATTN_SMEM_BYTES>>>(p_qkv, p_relh, p_relw, atth, attl);

    // 5) proj GEMM + unpartition + residual -> fp32 x1
    tc_gemm<1><<<dim3(768 / 128, (TOKS + 127) / 128), 256, GEMM_SMEM>>>(
        atth, attl, pwh, pwl, projb, p_x1, nullptr, nullptr, x,
        TOKS, 768, 768);

    // 6) LN2 -> bf16 hi/lo
    ln_kernel<<<PIX, 256>>>(p_x1, n2g, n2b, ln2h, ln2l, 0);

    // 7) MLP fc1 + GELU -> bf16 hi/lo
    tc_gemm<2><<<dim3(3072 / 128, PIX / 128), 256, GEMM_SMEM>>>(
        ln2h, ln2l, w1h, w1l, b1, nullptr, mlph, mlpl, nullptr,
        PIX, 3072, 768);

    // 8) MLP fc2 + residual -> final fp32 output
    tc_gemm<3><<<dim3(768 / 128, PIX / 128), 256, GEMM_SMEM>>>(
        mlph, mlpl, w2h, w2l, b2, out, nullptr, nullptr, p_x1,
        PIX, 768, 3072);

    (void)in_sizes; (void)n_in; (void)out_size;
}